// round 3
// baseline (speedup 1.0000x reference)
#include <cuda_runtime.h>
#include <math.h>

#define N 4096
#define G (3 * N)
#define CCHUNK 32          // rows per colmv block

// ---------------- device scratch ----------------
__device__ float g_t[N];        // logits buffer
__device__ float g_vec[N];      // softmax output
__device__ float g_sk[N];       // GRU hidden state
__device__ float g_u[N];        // u = W2 @ sk
__device__ float g_xk[N];       // x_k
__device__ float g_gi[G];       // w_ih @ xk
__device__ float g_gh[G];       // w_hh @ sk
__device__ float g_Pr[3];       // accumulated probabilities

// ---------------- kernels ----------------

__global__ void init_kernel() {
    int i = blockIdx.x * blockDim.x + threadIdx.x;
    if (i < N) g_t[i] = 0.0f;
    if (i < 3) g_Pr[i] = 0.0f;
}

// y[j] += sum_r x[r] * A[r, j]; float4 columns.
// grid: (N/1024, N/CCHUNK) = (4, 128), block: 256
__global__ void colmv_kernel(const float* __restrict__ A,
                             const float* __restrict__ x,
                             float* __restrict__ y,
                             int step, const int* __restrict__ Kp) {
    if (step >= *Kp) return;
    __shared__ float xs[CCHUNK];
    int j4 = blockIdx.x * blockDim.x + threadIdx.x;   // float4 column index
    int r0 = blockIdx.y * CCHUNK;
    if (threadIdx.x < CCHUNK) xs[threadIdx.x] = x[r0 + threadIdx.x];
    __syncthreads();
    const float4* A4 = (const float4*)A;
    float4 acc = make_float4(0.f, 0.f, 0.f, 0.f);
#pragma unroll 8
    for (int r = 0; r < CCHUNK; r++) {
        float4 a = __ldg(&A4[(size_t)(r0 + r) * (N / 4) + j4]);
        float s = xs[r];
        acc.x += s * a.x; acc.y += s * a.y; acc.z += s * a.z; acc.w += s * a.w;
    }
    float* yp = y + j4 * 4;
    atomicAdd(yp + 0, acc.x);
    atomicAdd(yp + 1, acc.y);
    atomicAdd(yp + 2, acc.z);
    atomicAdd(yp + 3, acc.w);
}

// Fused rowmv: rows [0,N) -> u = W2 @ x (and zero t[row]); rows [N, N+G) -> gh = w_hh @ x
// grid: N + G, block: 128
__global__ void rowmv2_kernel(const float* __restrict__ A0,   // W2 (N x N)
                              const float* __restrict__ A1,   // w_hh (G x N)
                              const float* __restrict__ x,    // sk
                              float* __restrict__ y0,         // u
                              float* __restrict__ y1,         // gh
                              float* __restrict__ t_zero,
                              int step, const int* __restrict__ Kp) {
    if (step >= *Kp) return;
    int row = blockIdx.x;
    const float* Arow;
    float* ydst;
    if (row < N) {
        Arow = A0 + (size_t)row * N;
        ydst = y0 + row;
        if (threadIdx.x == 0) t_zero[row] = 0.0f;
    } else {
        Arow = A1 + (size_t)(row - N) * N;
        ydst = y1 + (row - N);
    }
    const float4* A4 = (const float4*)Arow;
    const float4* x4 = (const float4*)x;
    float acc = 0.0f;
#pragma unroll 8
    for (int i = threadIdx.x; i < N / 4; i += 128) {
        float4 a = __ldg(&A4[i]);
        float4 b = __ldg(&x4[i]);
        acc += a.x * b.x + a.y * b.y + a.z * b.z + a.w * b.w;
    }
#pragma unroll
    for (int o = 16; o; o >>= 1) acc += __shfl_down_sync(0xffffffffu, acc, o);
    __shared__ float sh[4];
    if ((threadIdx.x & 31) == 0) sh[threadIdx.x >> 5] = acc;
    __syncthreads();
    if (threadIdx.x == 0) *ydst = sh[0] + sh[1] + sh[2] + sh[3];
}

// Plain rowmv: y[row] = dot(A[row], x).  grid: rows, block: 128
__global__ void rowmv_kernel(const float* __restrict__ A,
                             const float* __restrict__ x,
                             float* __restrict__ y,
                             int step, const int* __restrict__ Kp) {
    if (step >= *Kp) return;
    int row = blockIdx.x;
    const float4* A4 = (const float4*)(A + (size_t)row * N);
    const float4* x4 = (const float4*)x;
    float acc = 0.0f;
#pragma unroll 8
    for (int i = threadIdx.x; i < N / 4; i += 128) {
        float4 a = __ldg(&A4[i]);
        float4 b = __ldg(&x4[i]);
        acc += a.x * b.x + a.y * b.y + a.z * b.z + a.w * b.w;
    }
#pragma unroll
    for (int o = 16; o; o >>= 1) acc += __shfl_down_sync(0xffffffffu, acc, o);
    __shared__ float sh[4];
    if ((threadIdx.x & 31) == 0) sh[threadIdx.x >> 5] = acc;
    __syncthreads();
    if (threadIdx.x == 0) y[row] = sh[0] + sh[1] + sh[2] + sh[3];
}

// out = softmax(t) over N; zeroes z1[0:n1]. single block 1024 threads
__global__ void softmax_kernel(const float* __restrict__ t,
                               float* __restrict__ out,
                               float* z1, int n1,
                               int step, const int* __restrict__ Kp) {
    if (step >= *Kp) return;
    int tid = threadIdx.x;
    __shared__ float red[32];

    float m = -INFINITY;
    for (int i = tid; i < N; i += 1024) m = fmaxf(m, t[i]);
#pragma unroll
    for (int o = 16; o; o >>= 1) m = fmaxf(m, __shfl_down_sync(0xffffffffu, m, o));
    if ((tid & 31) == 0) red[tid >> 5] = m;
    __syncthreads();
    if (tid < 32) {
        float v = red[tid];
#pragma unroll
        for (int o = 16; o; o >>= 1) v = fmaxf(v, __shfl_down_sync(0xffffffffu, v, o));
        if (tid == 0) red[0] = v;
    }
    __syncthreads();
    float M = red[0];
    __syncthreads();

    float s = 0.0f;
    for (int i = tid; i < N; i += 1024) {
        float e = expf(t[i] - M);
        out[i] = e;
        s += e;
    }
#pragma unroll
    for (int o = 16; o; o >>= 1) s += __shfl_down_sync(0xffffffffu, s, o);
    if ((tid & 31) == 0) red[tid >> 5] = s;
    __syncthreads();
    if (tid < 32) {
        float v = red[tid];
#pragma unroll
        for (int o = 16; o; o >>= 1) v += __shfl_down_sync(0xffffffffu, v, o);
        if (tid == 0) red[0] = v;
    }
    __syncthreads();
    float inv = 1.0f / red[0];
    for (int i = tid; i < N; i += 1024) out[i] *= inv;

    if (z1) for (int i = tid; i < n1; i += 1024) z1[i] = 0.0f;
}

// Fused GRU elementwise + W3 feature dot + 3-label softmax accumulation.
// single block of 1024 threads, no atomics.
__global__ void gru_accum_kernel(const float* __restrict__ W3,
                                 int step, const int* __restrict__ Kp) {
    if (step >= *Kp) return;
    int tid = threadIdx.x;
    float l0 = 0.0f, l1 = 0.0f, l2 = 0.0f;

    for (int i = tid; i < N; i += 1024) {
        float h = g_sk[i];
        float x = g_xk[i];
        float ir = g_gi[i],         hr = g_gh[i];
        float iz = g_gi[N + i],     hz = g_gh[N + i];
        float in = g_gi[2 * N + i], hn = g_gh[2 * N + i];
        float r = 1.0f / (1.0f + expf(-(ir + hr)));
        float z = 1.0f / (1.0f + expf(-(iz + hz)));
        float nn = tanhf(in + r * hn);
        float hnew = (1.0f - z) * nn + z * h;
        g_sk[i] = hnew;

        float ad = fabsf(hnew - x);
        float pr = hnew * x;
        const float* w0 = W3 + (size_t)i * 3;
        const float* w1 = W3 + (size_t)(N + i) * 3;
        const float* w2 = W3 + (size_t)(2 * N + i) * 3;
        const float* w3 = W3 + (size_t)(3 * N + i) * 3;
        l0 += w0[0] * hnew + w1[0] * x + w2[0] * ad + w3[0] * pr;
        l1 += w0[1] * hnew + w1[1] * x + w2[1] * ad + w3[1] * pr;
        l2 += w0[2] * hnew + w1[2] * x + w2[2] * ad + w3[2] * pr;
    }
#pragma unroll
    for (int o = 16; o; o >>= 1) {
        l0 += __shfl_down_sync(0xffffffffu, l0, o);
        l1 += __shfl_down_sync(0xffffffffu, l1, o);
        l2 += __shfl_down_sync(0xffffffffu, l2, o);
    }
    __shared__ float s0[32], s1[32], s2[32];
    if ((tid & 31) == 0) {
        s0[tid >> 5] = l0; s1[tid >> 5] = l1; s2[tid >> 5] = l2;
    }
    __syncthreads();
    if (tid == 0) {
        float a = 0.f, b = 0.f, c = 0.f;
#pragma unroll
        for (int w = 0; w < 32; w++) { a += s0[w]; b += s1[w]; c += s2[w]; }
        float m = fmaxf(a, fmaxf(b, c));
        float ea = expf(a - m), eb = expf(b - m), ec = expf(c - m);
        float s = ea + eb + ec;
        g_Pr[0] += ea / s;
        g_Pr[1] += eb / s;
        g_Pr[2] += ec / s;
    }
}

__global__ void final_kernel(float* __restrict__ out, const int* __restrict__ Kp) {
    int i = threadIdx.x;
    if (i < 3) out[i] = g_Pr[i] / (float)(*Kp);
}

// ---------------- host launch ----------------
extern "C" void kernel_launch(void* const* d_in, const int* in_sizes, int n_in,
                              void* d_out, int out_size) {
    const float* M_h   = (const float*)d_in[0];
    const float* M_p   = (const float*)d_in[1];
    const float* w1    = (const float*)d_in[2];
    const float* W2    = (const float*)d_in[3];
    const float* W3    = (const float*)d_in[4];
    const float* w_ih  = (const float*)d_in[5];
    const float* w_hh  = (const float*)d_in[6];
    const int*   Kp    = (const int*)d_in[7];
    float* out = (float*)d_out;

    float *t, *vec, *sk, *u, *xk, *gi, *gh;
    cudaGetSymbolAddress((void**)&t,   g_t);
    cudaGetSymbolAddress((void**)&vec, g_vec);
    cudaGetSymbolAddress((void**)&sk,  g_sk);
    cudaGetSymbolAddress((void**)&u,   g_u);
    cudaGetSymbolAddress((void**)&xk,  g_xk);
    cudaGetSymbolAddress((void**)&gi,  g_gi);
    cudaGetSymbolAddress((void**)&gh,  g_gh);

    dim3 cgrid(N / 1024, N / CCHUNK);   // (4, 128)

    // prologue: alpha = softmax(w1^T M_h); sk0 = alpha @ M_h
    init_kernel<<<(N + 1023) / 1024, 1024>>>();
    colmv_kernel<<<cgrid, 256>>>(M_h, w1, t, 0, Kp);
    softmax_kernel<<<1, 1024>>>(t, vec, sk, N, 0, Kp);
    colmv_kernel<<<cgrid, 256>>>(M_h, vec, sk, 0, Kp);

    const int MAX_STEPS = 8;
    for (int s = 0; s < MAX_STEPS; s++) {
        // u = W2 @ sk ; gh = w_hh @ sk ; zero t
        rowmv2_kernel<<<N + G, 128>>>(W2, w_hh, sk, u, gh, t, s, Kp);
        // logits = u^T @ M_p
        colmv_kernel<<<cgrid, 256>>>(M_p, u, t, s, Kp);
        // beta = softmax(logits); zero xk
        softmax_kernel<<<1, 1024>>>(t, vec, xk, N, s, Kp);
        // xk = beta^T @ M_p
        colmv_kernel<<<cgrid, 256>>>(M_p, vec, xk, s, Kp);
        // gi = w_ih @ xk
        rowmv_kernel<<<G, 128>>>(w_ih, xk, gi, s, Kp);
        // GRU + feature dot + label softmax accumulation
        gru_accum_kernel<<<1, 1024>>>(W3, s, Kp);
    }

    final_kernel<<<1, 32>>>(out, Kp);
}

// round 4
// speedup vs baseline: 1.0034x; 1.0034x over previous
#include <cuda_runtime.h>
#include <math.h>

#define N 4096
#define G (3 * N)
#define CCHUNK 32          // rows per colmv block

// ---------------- device scratch ----------------
__device__ float g_t[N];        // logits buffer
__device__ float g_vec[N];      // softmax output
__device__ float g_sk[N];       // GRU hidden state
__device__ float g_u[N];        // u = W2 @ sk
__device__ float g_xk[N];       // x_k
__device__ float g_gi[G];       // w_ih @ xk
__device__ float g_gh[G];       // w_hh @ sk
__device__ float g_Pr[3];       // accumulated probabilities

// ---------------- kernels ----------------

__global__ void init_kernel() {
    int i = blockIdx.x * blockDim.x + threadIdx.x;
    if (i < N) g_t[i] = 0.0f;
    if (i < 3) g_Pr[i] = 0.0f;
}

// y[j] += sum_r x[r] * A[r, j]; float4 columns.
// grid: (N/1024, N/CCHUNK) = (4, 128), block: 256
__global__ void colmv_kernel(const float* __restrict__ A,
                             const float* __restrict__ x,
                             float* __restrict__ y,
                             int step, const int* __restrict__ Kp) {
    if (step >= *Kp) return;
    __shared__ float xs[CCHUNK];
    int j4 = blockIdx.x * blockDim.x + threadIdx.x;   // float4 column index
    int r0 = blockIdx.y * CCHUNK;
    if (threadIdx.x < CCHUNK) xs[threadIdx.x] = x[r0 + threadIdx.x];
    __syncthreads();
    const float4* A4 = (const float4*)A;
    float4 acc = make_float4(0.f, 0.f, 0.f, 0.f);
#pragma unroll 8
    for (int r = 0; r < CCHUNK; r++) {
        float4 a = __ldg(&A4[(size_t)(r0 + r) * (N / 4) + j4]);
        float s = xs[r];
        acc.x += s * a.x; acc.y += s * a.y; acc.z += s * a.z; acc.w += s * a.w;
    }
    float* yp = y + j4 * 4;
    atomicAdd(yp + 0, acc.x);
    atomicAdd(yp + 1, acc.y);
    atomicAdd(yp + 2, acc.z);
    atomicAdd(yp + 3, acc.w);
}

// Fused rowmv: rows [0,N) -> u = W2 @ x (and zero t[row]); rows [N, N+G) -> gh = w_hh @ x
// grid: N + G, block: 128
__global__ void rowmv2_kernel(const float* __restrict__ A0,   // W2 (N x N)
                              const float* __restrict__ A1,   // w_hh (G x N)
                              const float* __restrict__ x,    // sk
                              float* __restrict__ y0,         // u
                              float* __restrict__ y1,         // gh
                              float* __restrict__ t_zero,
                              int step, const int* __restrict__ Kp) {
    if (step >= *Kp) return;
    int row = blockIdx.x;
    const float* Arow;
    float* ydst;
    if (row < N) {
        Arow = A0 + (size_t)row * N;
        ydst = y0 + row;
        if (threadIdx.x == 0) t_zero[row] = 0.0f;
    } else {
        Arow = A1 + (size_t)(row - N) * N;
        ydst = y1 + (row - N);
    }
    const float4* A4 = (const float4*)Arow;
    const float4* x4 = (const float4*)x;
    float acc = 0.0f;
#pragma unroll 8
    for (int i = threadIdx.x; i < N / 4; i += 128) {
        float4 a = __ldg(&A4[i]);
        float4 b = __ldg(&x4[i]);
        acc += a.x * b.x + a.y * b.y + a.z * b.z + a.w * b.w;
    }
#pragma unroll
    for (int o = 16; o; o >>= 1) acc += __shfl_down_sync(0xffffffffu, acc, o);
    __shared__ float sh[4];
    if ((threadIdx.x & 31) == 0) sh[threadIdx.x >> 5] = acc;
    __syncthreads();
    if (threadIdx.x == 0) *ydst = sh[0] + sh[1] + sh[2] + sh[3];
}

// Plain rowmv: y[row] = dot(A[row], x).  grid: rows, block: 128
__global__ void rowmv_kernel(const float* __restrict__ A,
                             const float* __restrict__ x,
                             float* __restrict__ y,
                             int step, const int* __restrict__ Kp) {
    if (step >= *Kp) return;
    int row = blockIdx.x;
    const float4* A4 = (const float4*)(A + (size_t)row * N);
    const float4* x4 = (const float4*)x;
    float acc = 0.0f;
#pragma unroll 8
    for (int i = threadIdx.x; i < N / 4; i += 128) {
        float4 a = __ldg(&A4[i]);
        float4 b = __ldg(&x4[i]);
        acc += a.x * b.x + a.y * b.y + a.z * b.z + a.w * b.w;
    }
#pragma unroll
    for (int o = 16; o; o >>= 1) acc += __shfl_down_sync(0xffffffffu, acc, o);
    __shared__ float sh[4];
    if ((threadIdx.x & 31) == 0) sh[threadIdx.x >> 5] = acc;
    __syncthreads();
    if (threadIdx.x == 0) y[row] = sh[0] + sh[1] + sh[2] + sh[3];
}

// out = softmax(t) over N; zeroes z1[0:n1]. single block 1024 threads
__global__ void softmax_kernel(const float* __restrict__ t,
                               float* __restrict__ out,
                               float* z1, int n1,
                               int step, const int* __restrict__ Kp) {
    if (step >= *Kp) return;
    int tid = threadIdx.x;
    __shared__ float red[32];

    float m = -INFINITY;
    for (int i = tid; i < N; i += 1024) m = fmaxf(m, t[i]);
#pragma unroll
    for (int o = 16; o; o >>= 1) m = fmaxf(m, __shfl_down_sync(0xffffffffu, m, o));
    if ((tid & 31) == 0) red[tid >> 5] = m;
    __syncthreads();
    if (tid < 32) {
        float v = red[tid];
#pragma unroll
        for (int o = 16; o; o >>= 1) v = fmaxf(v, __shfl_down_sync(0xffffffffu, v, o));
        if (tid == 0) red[0] = v;
    }
    __syncthreads();
    float M = red[0];
    __syncthreads();

    float s = 0.0f;
    for (int i = tid; i < N; i += 1024) {
        float e = expf(t[i] - M);
        out[i] = e;
        s += e;
    }
#pragma unroll
    for (int o = 16; o; o >>= 1) s += __shfl_down_sync(0xffffffffu, s, o);
    if ((tid & 31) == 0) red[tid >> 5] = s;
    __syncthreads();
    if (tid < 32) {
        float v = red[tid];
#pragma unroll
        for (int o = 16; o; o >>= 1) v += __shfl_down_sync(0xffffffffu, v, o);
        if (tid == 0) red[0] = v;
    }
    __syncthreads();
    float inv = 1.0f / red[0];
    for (int i = tid; i < N; i += 1024) out[i] *= inv;

    if (z1) for (int i = tid; i < n1; i += 1024) z1[i] = 0.0f;
}

// Fused GRU elementwise + W3 feature dot + 3-label softmax accumulation.
// single block of 1024 threads, no atomics.
__global__ void gru_accum_kernel(const float* __restrict__ W3,
                                 int step, const int* __restrict__ Kp) {
    if (step >= *Kp) return;
    int tid = threadIdx.x;
    float l0 = 0.0f, l1 = 0.0f, l2 = 0.0f;

    for (int i = tid; i < N; i += 1024) {
        float h = g_sk[i];
        float x = g_xk[i];
        float ir = g_gi[i],         hr = g_gh[i];
        float iz = g_gi[N + i],     hz = g_gh[N + i];
        float in = g_gi[2 * N + i], hn = g_gh[2 * N + i];
        float r = 1.0f / (1.0f + expf(-(ir + hr)));
        float z = 1.0f / (1.0f + expf(-(iz + hz)));
        float nn = tanhf(in + r * hn);
        float hnew = (1.0f - z) * nn + z * h;
        g_sk[i] = hnew;

        float ad = fabsf(hnew - x);
        float pr = hnew * x;
        const float* w0 = W3 + (size_t)i * 3;
        const float* w1 = W3 + (size_t)(N + i) * 3;
        const float* w2 = W3 + (size_t)(2 * N + i) * 3;
        const float* w3 = W3 + (size_t)(3 * N + i) * 3;
        l0 += w0[0] * hnew + w1[0] * x + w2[0] * ad + w3[0] * pr;
        l1 += w0[1] * hnew + w1[1] * x + w2[1] * ad + w3[1] * pr;
        l2 += w0[2] * hnew + w1[2] * x + w2[2] * ad + w3[2] * pr;
    }
#pragma unroll
    for (int o = 16; o; o >>= 1) {
        l0 += __shfl_down_sync(0xffffffffu, l0, o);
        l1 += __shfl_down_sync(0xffffffffu, l1, o);
        l2 += __shfl_down_sync(0xffffffffu, l2, o);
    }
    __shared__ float s0[32], s1[32], s2[32];
    if ((tid & 31) == 0) {
        s0[tid >> 5] = l0; s1[tid >> 5] = l1; s2[tid >> 5] = l2;
    }
    __syncthreads();
    if (tid == 0) {
        float a = 0.f, b = 0.f, c = 0.f;
#pragma unroll
        for (int w = 0; w < 32; w++) { a += s0[w]; b += s1[w]; c += s2[w]; }
        float m = fmaxf(a, fmaxf(b, c));
        float ea = expf(a - m), eb = expf(b - m), ec = expf(c - m);
        float s = ea + eb + ec;
        g_Pr[0] += ea / s;
        g_Pr[1] += eb / s;
        g_Pr[2] += ec / s;
    }
}

__global__ void final_kernel(float* __restrict__ out, const int* __restrict__ Kp) {
    int i = threadIdx.x;
    if (i < 3) out[i] = g_Pr[i] / (float)(*Kp);
}

// ---------------- host launch ----------------
extern "C" void kernel_launch(void* const* d_in, const int* in_sizes, int n_in,
                              void* d_out, int out_size) {
    const float* M_h   = (const float*)d_in[0];
    const float* M_p   = (const float*)d_in[1];
    const float* w1    = (const float*)d_in[2];
    const float* W2    = (const float*)d_in[3];
    const float* W3    = (const float*)d_in[4];
    const float* w_ih  = (const float*)d_in[5];
    const float* w_hh  = (const float*)d_in[6];
    const int*   Kp    = (const int*)d_in[7];
    float* out = (float*)d_out;

    float *t, *vec, *sk, *u, *xk, *gi, *gh;
    cudaGetSymbolAddress((void**)&t,   g_t);
    cudaGetSymbolAddress((void**)&vec, g_vec);
    cudaGetSymbolAddress((void**)&sk,  g_sk);
    cudaGetSymbolAddress((void**)&u,   g_u);
    cudaGetSymbolAddress((void**)&xk,  g_xk);
    cudaGetSymbolAddress((void**)&gi,  g_gi);
    cudaGetSymbolAddress((void**)&gh,  g_gh);

    dim3 cgrid(N / 1024, N / CCHUNK);   // (4, 128)

    // prologue: alpha = softmax(w1^T M_h); sk0 = alpha @ M_h
    init_kernel<<<(N + 1023) / 1024, 1024>>>();
    colmv_kernel<<<cgrid, 256>>>(M_h, w1, t, 0, Kp);
    softmax_kernel<<<1, 1024>>>(t, vec, sk, N, 0, Kp);
    colmv_kernel<<<cgrid, 256>>>(M_h, vec, sk, 0, Kp);

    const int MAX_STEPS = 8;
    for (int s = 0; s < MAX_STEPS; s++) {
        // u = W2 @ sk ; gh = w_hh @ sk ; zero t
        rowmv2_kernel<<<N + G, 128>>>(W2, w_hh, sk, u, gh, t, s, Kp);
        // logits = u^T @ M_p
        colmv_kernel<<<cgrid, 256>>>(M_p, u, t, s, Kp);
        // beta = softmax(logits); zero xk
        softmax_kernel<<<1, 1024>>>(t, vec, xk, N, s, Kp);
        // xk = beta^T @ M_p
        colmv_kernel<<<cgrid, 256>>>(M_p, vec, xk, s, Kp);
        // gi = w_ih @ xk
        rowmv_kernel<<<G, 128>>>(w_ih, xk, gi, s, Kp);
        // GRU + feature dot + label softmax accumulation
        gru_accum_kernel<<<1, 1024>>>(W3, s, Kp);
    }

    final_kernel<<<1, 32>>>(out, Kp);
}